// round 6
// baseline (speedup 1.0000x reference)
#include <cuda_runtime.h>
#include <cuda_bf16.h>

#define BB 8
#define FF 128
#define PP 256
#define TT 2048

// warp-autonomous: each warp owns 32 ticks x 32 pe-channels. No smem, no barriers.
__global__ __launch_bounds__(128)
void flash_reco_kernel(const float* __restrict__ pe,     // [B,F,P]
                       const float* __restrict__ ftime,  // [B,F]
                       const float* __restrict__ conf,   // [B,F]
                       const float* __restrict__ sigma_ptr,
                       float* __restrict__ out)          // [B,P,T]
{
    const int lane = threadIdx.x & 31;
    const int warp = threadIdx.x >> 5;
    const int b    = blockIdx.z;
    const int p0   = blockIdx.y * 32;
    const int t0   = blockIdx.x * 128 + warp * 32;

    const float sigma = sigma_ptr ? __ldg(sigma_ptr) : 1.0f;
    const float inv_s = 1.0f / sigma;
    const float W     = 10.0f * sigma;            // exp(-50) ~ 2e-22: negligible
    // full-lattice Gaussian sum for interior flashes: sigma*sqrt(2*pi),
    // theta-function correction < e^(-2*pi^2*sigma^2) (2.7e-9 at sigma=1)
    const float inv_anorm = 1.0f / (sigma * 2.5066282746310002f + 1e-10f);
    const bool  analytic_ok = (sigma >= 0.9f);

    // ---- prefix: lane owns flashes f = c*32+lane, c=0..3 ----
    float tb[4], cf[4];
    #pragma unroll
    for (int c = 0; c < 4; ++c) {
        const int f = c * 32 + lane;
        tb[c] = fminf(fmaxf(__ldg(&ftime[b * FF + f]) * (float)TT, 0.0f),
                      (float)(TT - 1));
        cf[c] = __ldg(&conf[b * FF + f]);
    }

    const float t_f = (float)(t0 + lane);
    const float wlo = (float)t0 - W;
    const float whi = (float)(t0 + 31) + W;

    unsigned long long acc[16];                   // 16 packed f32x2 = 32 p's
    #pragma unroll
    for (int j = 0; j < 16; ++j) acc[j] = 0ull;

    #pragma unroll
    for (int c = 0; c < 4; ++c) {
        unsigned mask =
            __ballot_sync(0xffffffffu, tb[c] >= wlo && tb[c] <= whi);
        while (mask) {                            // ascending f: deterministic
            const int k = __ffs(mask) - 1;
            mask &= mask - 1;
            const float tbk = __shfl_sync(0xffffffffu, tb[c], k);
            const float cfk = __shfl_sync(0xffffffffu, cf[c], k);

            // normalizer: warp-uniform branch (tbk uniform across lanes)
            float csk;
            if (analytic_ok && tbk >= W && tbk <= (float)(TT - 1) - W) {
                csk = cfk * inv_anorm;
            } else {                              // edge / small-sigma: cooperative
                const int lo = max(0, (int)ceilf(tbk - W));
                const int hi = min(TT - 1, (int)floorf(tbk + W));
                float s = 0.0f;
                for (int t = lo + lane; t <= hi; t += 32) {
                    const float zz = ((float)t - tbk) * inv_s;
                    s += __expf(-0.5f * zz * zz);
                }
                #pragma unroll
                for (int d = 16; d > 0; d >>= 1)
                    s += __shfl_xor_sync(0xffffffffu, s, d);
                csk = cfk / (s + 1e-10f);
            }

            const float z = (t_f - tbk) * inv_s;
            const float w = csk * __expf(-0.5f * z * z);
            unsigned long long ww;
            asm("mov.b64 %0, {%1, %1};" : "=l"(ww) : "f"(w));

            const int f = c * 32 + k;
            const ulonglong2* row = reinterpret_cast<const ulonglong2*>(
                pe + (b * FF + f) * PP + p0);     // uniform broadcast rows
            #pragma unroll
            for (int q = 0; q < 8; ++q) {
                ulonglong2 v = __ldg(&row[q]);    // LDG.128, 1 wavefront each
                asm("fma.rn.f32x2 %0, %1, %2, %0;"
                    : "+l"(acc[2 * q])     : "l"(ww), "l"(v.x));
                asm("fma.rn.f32x2 %0, %1, %2, %0;"
                    : "+l"(acc[2 * q + 1]) : "l"(ww), "l"(v.y));
            }
        }
    }

    // ---- stores: lanes span contiguous t -> 32 coalesced 128B stores ----
    float* op = out + (size_t)(b * PP + p0) * TT + t0 + lane;
    #pragma unroll
    for (int j = 0; j < 16; ++j) {
        float lo, hi;
        asm("mov.b64 {%0, %1}, %2;" : "=f"(lo), "=f"(hi) : "l"(acc[j]));
        op[(size_t)(2 * j)     * TT] = lo;
        op[(size_t)(2 * j + 1) * TT] = hi;
    }
}

extern "C" void kernel_launch(void* const* d_in, const int* in_sizes, int n_in,
                              void* d_out, int out_size)
{
    const float* pe = (const float*)d_in[0];           // flashes_pe [B,F,P]
    const float* tm = (const float*)d_in[1];           // flashes_time [B,F,1]
    const float* cf = (const float*)d_in[2];           // flashes_confidence [B,F,1]
    const float* sg = (n_in >= 4) ? (const float*)d_in[n_in - 1] : nullptr;  // sigma last

    dim3 grid(TT / 128, PP / 32, BB);                  // 16 x 8 x 8 = 1024 blocks
    flash_reco_kernel<<<grid, 128>>>(pe, tm, cf, sg, (float*)d_out);
}

// round 7
// speedup vs baseline: 1.0654x; 1.0654x over previous
#include <cuda_runtime.h>
#include <cuda_bf16.h>

#define BB 8
#define FF 128
#define PP 256
#define TT 2048

// warp-autonomous: warp owns 32 ticks x 32 pe-channels. No smem, no barriers.
// Lane owns flashes f = 4*lane + j (j=0..3) via float4 prefix loads.
__global__ __launch_bounds__(128, 7)
void flash_reco_kernel(const float* __restrict__ pe,     // [B,F,P]
                       const float* __restrict__ ftime,  // [B,F]
                       const float* __restrict__ conf,   // [B,F]
                       const float* __restrict__ sigma_ptr,
                       float* __restrict__ out)          // [B,P,T]
{
    const int lane = threadIdx.x & 31;
    const int warp = threadIdx.x >> 5;
    const int b    = blockIdx.z;
    const int p0   = blockIdx.y * 32;
    const int t0   = blockIdx.x * 128 + warp * 32;

    const float sigma = sigma_ptr ? __ldg(sigma_ptr) : 1.0f;
    const float inv_s = 1.0f / sigma;
    const float W     = 7.0f * sigma;             // exp(-24.5) ~ 2e-11: negligible
    // full-lattice Gaussian sum for interior flashes: sigma*sqrt(2*pi),
    // theta-function correction < e^(-2*pi^2*sigma^2) (2.7e-9 at sigma=1)
    const float inv_anorm = 1.0f / (sigma * 2.5066282746310002f + 1e-10f);
    const bool  analytic_ok = (sigma >= 0.9f);

    // ---- prefix: vectorized, lane owns f = 4*lane+j ----
    float4 tb4 = __ldg(reinterpret_cast<const float4*>(ftime + b * FF) + lane);
    float4 cf4 = __ldg(reinterpret_cast<const float4*>(conf  + b * FF) + lane);
    tb4.x = fminf(fmaxf(tb4.x * (float)TT, 0.0f), (float)(TT - 1));
    tb4.y = fminf(fmaxf(tb4.y * (float)TT, 0.0f), (float)(TT - 1));
    tb4.z = fminf(fmaxf(tb4.z * (float)TT, 0.0f), (float)(TT - 1));
    tb4.w = fminf(fmaxf(tb4.w * (float)TT, 0.0f), (float)(TT - 1));

    const float t_f = (float)(t0 + lane);
    const float wlo = (float)t0 - W;
    const float whi = (float)(t0 + 31) + W;

    const float tbs[4] = {tb4.x, tb4.y, tb4.z, tb4.w};
    const float cfs[4] = {cf4.x, cf4.y, cf4.z, cf4.w};

    // ---- prefetch pe rows of this lane's relevant flashes (overlapped RTs) ----
    #pragma unroll
    for (int j = 0; j < 4; ++j) {
        if (tbs[j] >= wlo && tbs[j] <= whi) {
            const float* row = pe + (b * FF + (4 * lane + j)) * PP + p0;  // 128B line
            asm volatile("prefetch.global.L1 [%0];" :: "l"(row));
        }
    }

    unsigned long long acc[16];                   // 16 packed f32x2 = 32 p's
    #pragma unroll
    for (int j = 0; j < 16; ++j) acc[j] = 0ull;

    #pragma unroll
    for (int j = 0; j < 4; ++j) {
        unsigned mask =
            __ballot_sync(0xffffffffu, tbs[j] >= wlo && tbs[j] <= whi);
        while (mask) {                            // fixed order: deterministic
            const int k = __ffs(mask) - 1;
            mask &= mask - 1;
            const float tbk = __shfl_sync(0xffffffffu, tbs[j], k);
            const float cfk = __shfl_sync(0xffffffffu, cfs[j], k);

            // normalizer: warp-uniform branch (tbk uniform across lanes)
            float csk;
            if (analytic_ok && tbk >= W && tbk <= (float)(TT - 1) - W) {
                csk = cfk * inv_anorm;
            } else {                              // edge / small-sigma: cooperative
                const int lo = max(0, (int)ceilf(tbk - W));
                const int hi = min(TT - 1, (int)floorf(tbk + W));
                float s = 0.0f;
                for (int t = lo + lane; t <= hi; t += 32) {
                    const float zz = ((float)t - tbk) * inv_s;
                    s += __expf(-0.5f * zz * zz);
                }
                #pragma unroll
                for (int d = 16; d > 0; d >>= 1)
                    s += __shfl_xor_sync(0xffffffffu, s, d);
                csk = cfk / (s + 1e-10f);
            }

            const float z = (t_f - tbk) * inv_s;
            const float w = csk * __expf(-0.5f * z * z);
            unsigned long long ww;
            asm("mov.b64 %0, {%1, %1};" : "=l"(ww) : "f"(w));

            const int f = 4 * k + j;
            const ulonglong2* row = reinterpret_cast<const ulonglong2*>(
                pe + (b * FF + f) * PP + p0);     // uniform broadcast, L1-hot
            #pragma unroll
            for (int q = 0; q < 8; ++q) {
                ulonglong2 v = __ldg(&row[q]);
                asm("fma.rn.f32x2 %0, %1, %2, %0;"
                    : "+l"(acc[2 * q])     : "l"(ww), "l"(v.x));
                asm("fma.rn.f32x2 %0, %1, %2, %0;"
                    : "+l"(acc[2 * q + 1]) : "l"(ww), "l"(v.y));
            }
        }
    }

    // ---- stores: lanes span contiguous t -> coalesced 128B warp stores ----
    float* op = out + (size_t)(b * PP + p0) * TT + t0 + lane;
    #pragma unroll
    for (int j = 0; j < 16; ++j) {
        float lo, hi;
        asm("mov.b64 {%0, %1}, %2;" : "=f"(lo), "=f"(hi) : "l"(acc[j]));
        op[(size_t)(2 * j)     * TT] = lo;
        op[(size_t)(2 * j + 1) * TT] = hi;
    }
}

extern "C" void kernel_launch(void* const* d_in, const int* in_sizes, int n_in,
                              void* d_out, int out_size)
{
    const float* pe = (const float*)d_in[0];           // flashes_pe [B,F,P]
    const float* tm = (const float*)d_in[1];           // flashes_time [B,F,1]
    const float* cf = (const float*)d_in[2];           // flashes_confidence [B,F,1]
    const float* sg = (n_in >= 4) ? (const float*)d_in[n_in - 1] : nullptr;  // sigma last

    dim3 grid(TT / 128, PP / 32, BB);                  // 16 x 8 x 8 = 1024 blocks
    flash_reco_kernel<<<grid, 128>>>(pe, tm, cf, sg, (float*)d_out);
}